// round 13
// baseline (speedup 1.0000x reference)
#include <cuda_runtime.h>
#include <cuda_bf16.h>
#include <cstdint>

// ---------------- problem constants ----------------
#define NB    32
#define CIN   128
#define HW    56
#define OC    256
#define HP    58
#define KTAPS 9
#define MTOT  (NB*HW*HW)             // 100352
#define NTILE (MTOT/128*2)           // 1568 tiles (784 bm x 2 bn)

#define X_ELEMS  (NB*CIN*HW*HW)      // 12,845,056
#define W_ELEMS  (OC*CIN*3*3)        // 294,912

// ---------------- smem layout: 4-stage K64 chunks ----------------
#define CROW   80                    // 64 data + 16 pad per row
#define CTILE  (128*CROW)            // 10240 per operand per chunk
#define STAGE  (2*CTILE)             // A + B = 20480
#define NSTAGE 4
#define SMEM_DYN (NSTAGE*STAGE)      // 81920
#define NCHUNK 18                    // 9 taps x 2 k-halves

// scratch (allocation-free rule: device globals)
__device__ int8_t g_xp[(size_t)NB*HP*HP*CIN];   // padded NHWC input
__device__ int8_t g_wt[(size_t)OC*KTAPS*CIN];   // K-major weights [oc][tap][ic]

// runtime-discovered dtype config
__device__ int g_mode_x;    // 0=int8 1=float32 2=int32 3=bf16
__device__ int g_mode_w;
__device__ int g_kind_s0;   // 0=bias(int32) 1=bias(f32) 2=scale(f32)
__device__ int g_kind_s1;

// ---------------- dtype detection (warp-parallel) ----------------
__device__ static int detect_mode(const void* p, int lane)
{
    const int*   ip = (const int*)p;
    const float* fp = (const float*)p;
    const __nv_bfloat16* bp = (const __nv_bfloat16*)p;
    bool i32 = true, f32 = true, b16 = true;
    for (int i = lane; i < 64; i += 32) {
        int v = ip[i];
        if (v < -128 || v > 127) i32 = false;
        float f = fp[i];
        if (!(f == floorf(f) && f >= -128.f && f <= 127.f)) f32 = false;
    }
    for (int i = lane; i < 128; i += 32) {
        float f = __bfloat162float(bp[i]);
        if (!(f == floorf(f) && f >= -128.f && f <= 127.f)) b16 = false;
    }
    i32 = __all_sync(0xFFFFFFFFu, i32);
    f32 = __all_sync(0xFFFFFFFFu, f32);
    b16 = __all_sync(0xFFFFFFFFu, b16);
    if (i32) return 2;
    if (f32) return 1;
    if (b16) return 3;
    return 0;
}

__device__ static int detect_kind(const void* p, int lane)
{
    const int*   ip = (const int*)p;
    const float* fp = (const float*)p;
    bool i32b = true, f32s = true, f32b = true;
    for (int i = lane; i < 64; i += 32) {
        int v = ip[i];
        if (v < -1000 || v > 1000) i32b = false;
        float f = fp[i];
        if (!(f >= 0.0009f && f <= 0.0101f)) f32s = false;
        if (!(f == floorf(f) && f >= -1000.f && f <= 1000.f)) f32b = false;
    }
    i32b = __all_sync(0xFFFFFFFFu, i32b);
    f32s = __all_sync(0xFFFFFFFFu, f32s);
    f32b = __all_sync(0xFFFFFFFFu, f32b);
    if (i32b) return 0;
    if (f32s) return 2;
    if (f32b) return 1;
    return 2;
}

__global__ void detect_kernel(const void* x, const void* w,
                              const void* s0, const void* s1)
{
    int warp = threadIdx.x >> 5, lane = threadIdx.x & 31;
    if (warp == 0) { int m = detect_mode(x, lane);  if (lane == 0) g_mode_x = m; }
    if (warp == 1) { int m = detect_mode(w, lane);  if (lane == 0) g_mode_w = m; }
    if (warp == 2) { int k = detect_kind(s0, lane); if (lane == 0) g_kind_s0 = k; }
    if (warp == 3) { int k = detect_kind(s1, lane); if (lane == 0) g_kind_s1 = k; }
}

__device__ __forceinline__ int load_elem(const void* p, size_t idx, int mode)
{
    switch (mode) {
        case 1:  return __float2int_rn(((const float*)p)[idx]);
        case 2:  return ((const int*)p)[idx];
        case 3:  return __float2int_rn(__bfloat162float(((const __nv_bfloat16*)p)[idx]));
        default: return ((const int8_t*)p)[idx];
    }
}

// ---------------- prep 1: NCHW -> padded NHWC ----------------
__global__ void pad_nhwc_kernel(const void* __restrict__ x)
{
    __shared__ int8_t smb[CIN * HW];
    int nb = blockIdx.x;
    int n  = nb / HP;
    int hp = nb - n * HP;
    int t  = threadIdx.x;                         // 128 threads
    int mode = g_mode_x;

    int8_t* xprow = g_xp + (size_t)(n * HP + hp) * HP * CIN;

    for (int idx = t; idx < HP * CIN / 16; idx += 128)
        ((int4*)xprow)[idx] = make_int4(0, 0, 0, 0);

    if (hp == 0 || hp == HP - 1) return;
    int h = hp - 1;

    for (int ii = t; ii < CIN * HW; ii += 128) {
        int c  = ii / HW;
        int wi = ii - c * HW;
        size_t gidx = (size_t)(n * CIN + c) * 3136 + (size_t)h * HW + wi;
        smb[ii] = (int8_t)load_elem(x, gidx, mode);
    }
    __syncthreads();

    #pragma unroll 4
    for (int i = 0; i < HW; ++i)
        xprow[(i + 1) * CIN + t] = smb[t * HW + i];
}

// ---------------- prep 2: OIHW -> [oc][kh][kw][ic] ----------------
__global__ void wt_transform_kernel(const void* __restrict__ w)
{
    int idx = blockIdx.x * 256 + threadIdx.x;
    int mode = g_mode_w;
    int oc  = idx / (KTAPS * CIN);
    int r   = idx - oc * (KTAPS * CIN);
    int tap = r >> 7;
    int ic  = r & 127;
    int kh  = tap / 3, kw = tap - kh * 3;
    size_t gidx = ((size_t)(oc * CIN + ic) * 3 + kh) * 3 + kw;
    g_wt[idx] = (int8_t)load_elem(w, gidx, mode);
}

// ---------------- PTX helpers ----------------
__device__ __forceinline__ void cpa16(uint32_t s, const void* g) {
    asm volatile("cp.async.cg.shared.global [%0], [%1], 16;\n" :: "r"(s), "l"(g));
}
__device__ __forceinline__ void ldm_x4(uint32_t addr, uint32_t& r0, uint32_t& r1,
                                       uint32_t& r2, uint32_t& r3) {
    asm volatile("ldmatrix.sync.aligned.m8n8.x4.shared.b16 {%0,%1,%2,%3}, [%4];\n"
                 : "=r"(r0), "=r"(r1), "=r"(r2), "=r"(r3) : "r"(addr));
}
__device__ __forceinline__ void mma8(int& d0, int& d1, int& d2, int& d3,
                                     uint32_t a0, uint32_t a1, uint32_t a2, uint32_t a3,
                                     uint32_t b0, uint32_t b1) {
    asm volatile("mma.sync.aligned.m16n8k32.row.col.s32.s8.s8.s32 "
                 "{%0,%1,%2,%3}, {%4,%5,%6,%7}, {%8,%9}, {%0,%1,%2,%3};\n"
                 : "+r"(d0), "+r"(d1), "+r"(d2), "+r"(d3)
                 : "r"(a0), "r"(a1), "r"(a2), "r"(a3), "r"(b0), "r"(b1));
}

// ---------------- main: persistent implicit-GEMM conv ----------------
// persistent CTAs; per tile: 128(M pixels) x 128(N oc); 8 warps (2m x 4n), warp 64x32.
// K = 18 chunks of 64; 4-stage ring, 3 chunks in flight, 1 sync per chunk.
__global__ void __launch_bounds__(256, 2)
conv_kernel(const void* __restrict__ sA, const void* __restrict__ sB,
            float* __restrict__ out)
{
    extern __shared__ __align__(128) int8_t smem[];
    const int tid  = threadIdx.x;
    const int lane = tid & 31, warp = tid >> 5;
    const int wm = warp & 1, wn = warp >> 1;      // wn in 0..3

    uint32_t sbase = (uint32_t)__cvta_generic_to_shared(smem);

    // loader mapping: thread t -> row t>>1, 32B half (t&1) of the 64B chunk row
    const int lrow = tid >> 1;
    const int lofs = (tid & 1) * 32;
    const uint32_t s_row = (uint32_t)(lrow * CROW + lofs);

    // ldmatrix lane decode
    const int q  = lane >> 3;
    const int lr = lane & 7;
    const int a_row_off  = (q & 1) * 8 + lr;
    const int a_k_off    = (q >> 1) * 16;
    const int b_tile_sel = (q >> 1);
    const int b_k_off    = (q & 1) * 16;

    // epilogue params (resolved once)
    const int k0 = g_kind_s0;
    const void* biasp; const float* scalep; int bias_f32;
    if (k0 == 2) { scalep = (const float*)sA; biasp = sB; bias_f32 = (g_kind_s1 == 1); }
    else         { biasp  = sA; bias_f32 = (k0 == 1); scalep = (const float*)sB; }
    const int gid = lane >> 2, tig = lane & 3;
    float* smf = (float*)smem;
    const int STRF = 132;     // floats; 128*132*4 = 67584 <= 81920

    for (int tile = blockIdx.x; tile < NTILE; tile += gridDim.x) {
        const int bm = tile >> 1;
        const int bn = tile & 1;

        int p  = bm * 128 + lrow;
        int n  = p / 3136;
        int s  = p - n * 3136;
        int oh = s / 56;
        int ow = s - oh * 56;
        const int8_t* abase = g_xp + (size_t)((n * HP + oh) * HP + ow) * CIN + lofs;
        const int8_t* bbase = g_wt + (size_t)(bn * 128 + lrow) * (KTAPS * CIN) + lofs;

        int acc[4][4][4];
        #pragma unroll
        for (int i = 0; i < 4; i++)
            #pragma unroll
            for (int j = 0; j < 4; j++)
                #pragma unroll
                for (int r = 0; r < 4; r++) acc[i][j][r] = 0;

        auto load_chunk = [&](int ci) {
            const int st   = ci & 3;
            const int tap  = ci >> 1;
            const int kofs = (ci & 1) * 64;
            const int kh = tap / 3, kw = tap - kh * 3;
            const uint32_t sa = sbase + st * STAGE + s_row;
            const int8_t* ga = abase + (kh * HP + kw) * CIN + kofs;
            cpa16(sa,      ga);
            cpa16(sa + 16, ga + 16);
            const uint32_t sb = sa + CTILE;
            const int8_t* gb = bbase + tap * CIN + kofs;
            cpa16(sb,      gb);
            cpa16(sb + 16, gb + 16);
            asm volatile("cp.async.commit_group;\n" ::: "memory");
        };

        // prologue: 3 chunks in flight
        load_chunk(0);
        load_chunk(1);
        load_chunk(2);

        for (int ci = 0; ci < NCHUNK; ++ci) {
            if (ci <= NCHUNK - 3)      asm volatile("cp.async.wait_group 2;\n" ::: "memory");
            else if (ci == NCHUNK - 2) asm volatile("cp.async.wait_group 1;\n" ::: "memory");
            else                       asm volatile("cp.async.wait_group 0;\n" ::: "memory");
            __syncthreads();        // chunk ci visible; slot (ci+3)%4 free

            if (ci + 3 < NCHUNK) load_chunk(ci + 3);   // overlaps compute of ci

            const uint32_t Ab = sbase + (ci & 3) * STAGE;
            const uint32_t Bb = Ab + CTILE;
            #pragma unroll
            for (int ks = 0; ks < 2; ++ks) {
                uint32_t a[4][4];
                #pragma unroll
                for (int i = 0; i < 4; i++) {
                    uint32_t addr = Ab + (uint32_t)((wm * 64 + i * 16 + a_row_off) * CROW
                                                    + a_k_off + ks * 32);
                    ldm_x4(addr, a[i][0], a[i][1], a[i][2], a[i][3]);
                }
                uint32_t b[4][2];
                #pragma unroll
                for (int jp = 0; jp < 2; jp++) {
                    uint32_t addr = Bb + (uint32_t)((wn * 32 + (jp * 2 + b_tile_sel) * 8 + lr) * CROW
                                                    + b_k_off + ks * 32);
                    uint32_t r0, r1, r2, r3;
                    ldm_x4(addr, r0, r1, r2, r3);
                    b[jp * 2][0] = r0;     b[jp * 2][1] = r1;
                    b[jp * 2 + 1][0] = r2; b[jp * 2 + 1][1] = r3;
                }
                #pragma unroll
                for (int i = 0; i < 4; i++)
                    #pragma unroll
                    for (int j = 0; j < 4; j++)
                        mma8(acc[i][j][0], acc[i][j][1], acc[i][j][2], acc[i][j][3],
                             a[i][0], a[i][1], a[i][2], a[i][3], b[j][0], b[j][1]);
            }
        }
        __syncthreads();   // stages fully read before epilogue reuses smem

        // ---- epilogue: requantize -> smem [oc][pixel] -> float32 NCHW ----
        #pragma unroll
        for (int j = 0; j < 4; j++) {
            int col0 = wn * 32 + j * 8 + tig * 2;                 // local oc within 128
            int oc0  = bn * 128 + col0;
            int bv0, bv1;
            if (bias_f32) { bv0 = __float2int_rn(((const float*)biasp)[oc0]);
                            bv1 = __float2int_rn(((const float*)biasp)[oc0 + 1]); }
            else          { bv0 = ((const int*)biasp)[oc0];
                            bv1 = ((const int*)biasp)[oc0 + 1]; }
            float sc0 = (0.02f * scalep[oc0])     / 0.05f;        // reference fp32 op order
            float sc1 = (0.02f * scalep[oc0 + 1]) / 0.05f;
            #pragma unroll
            for (int i = 0; i < 4; i++) {
                #pragma unroll
                for (int r = 0; r < 4; r++) {
                    int row = wm * 64 + i * 16 + gid + (r >> 1) * 8;
                    int cl  = col0 + (r & 1);
                    int v   = acc[i][j][r] + ((r & 1) ? bv1 : bv0);
                    float f = (float)v * ((r & 1) ? sc1 : sc0);
                    int qv  = __float2int_rn(f);                  // round-half-even
                    qv = max(-128, min(127, qv));
                    smf[cl * STRF + row] = (float)qv;
                }
            }
        }
        __syncthreads();

        // coalesced writeout: thread t -> oc row t>>1, 64-pixel half (t&1)
        {
            int cl  = tid >> 1;
            int px0 = (tid & 1) * 64;
            int oc  = bn * 128 + cl;
            int pp  = bm * 128 + px0;
            int nn  = pp / 3136;
            int ss  = pp - nn * 3136;             // 64 | 3136: chunk stays in-image
            float4*       dst = (float4*)(out + ((size_t)(nn * OC + oc)) * 3136 + ss);
            const float4* src = (const float4*)(smf + cl * STRF + px0);
            #pragma unroll
            for (int k = 0; k < 16; k++) dst[k] = src[k];
        }
        __syncthreads();   // writeout done before next tile's loads overwrite smem
    }
}

// ---------------- launch ----------------
extern "C" void kernel_launch(void* const* d_in, const int* in_sizes, int n_in,
                              void* d_out, int out_size)
{
    const void* xin = 0; const void* win = 0;
    const void* s0  = 0; const void* s1  = 0;
    for (int i = 0; i < n_in; i++) {
        if (in_sizes[i] == X_ELEMS)      xin = d_in[i];
        else if (in_sizes[i] == W_ELEMS) win = d_in[i];
        else if (!s0)                    s0  = d_in[i];
        else                             s1  = d_in[i];
    }

    detect_kernel<<<1, 128>>>(xin, win, s0, s1);
    pad_nhwc_kernel<<<NB * HP, 128>>>(xin);
    wt_transform_kernel<<<(OC * KTAPS * CIN) / 256, 256>>>(win);

    int nsm = 0;
    if (cudaDeviceGetAttribute(&nsm, cudaDevAttrMultiProcessorCount, 0) != cudaSuccess
        || nsm <= 0) nsm = 148;
    int grid = 2 * nsm;
    if (grid > NTILE) grid = NTILE;

    cudaFuncSetAttribute(conv_kernel, cudaFuncAttributeMaxDynamicSharedMemorySize,
                         SMEM_DYN);
    conv_kernel<<<grid, 256, SMEM_DYN>>>(s0, s1, (float*)d_out);
}

// round 14
// speedup vs baseline: 1.0327x; 1.0327x over previous
#include <cuda_runtime.h>
#include <cuda_bf16.h>
#include <cstdint>

// ---------------- problem constants ----------------
#define NB    32
#define CIN   128
#define HW    56
#define OC    256
#define HP    58
#define KTAPS 9
#define MTOT  (NB*HW*HW)             // 100352

#define X_ELEMS  (NB*CIN*HW*HW)      // 12,845,056
#define W_ELEMS  (OC*CIN*3*3)        // 294,912

// ---------------- smem layout: 4-stage K64 chunks ----------------
#define CROW   80                    // 64 data + 16 pad per row
#define CTILE  (128*CROW)            // 10240 per operand per chunk
#define STAGE  (2*CTILE)             // A + B = 20480
#define NSTAGE 4
#define SMEM_DYN (NSTAGE*STAGE)      // 81920
#define NCHUNK 18                    // 9 taps x 2 k-halves

// scratch (allocation-free rule: device globals)
__device__ int8_t g_xp[(size_t)NB*HP*HP*CIN];   // padded NHWC input
__device__ int8_t g_wt[(size_t)OC*KTAPS*CIN];   // K-major weights [oc][tap][ic]

// runtime-discovered dtype config
__device__ int g_mode_x;    // 0=int8 1=float32 2=int32 3=bf16
__device__ int g_mode_w;
__device__ int g_kind_s0;   // 0=bias(int32) 1=bias(f32) 2=scale(f32)
__device__ int g_kind_s1;

// ---------------- dtype detection (warp-parallel) ----------------
__device__ static int detect_mode(const void* p, int lane)
{
    const int*   ip = (const int*)p;
    const float* fp = (const float*)p;
    const __nv_bfloat16* bp = (const __nv_bfloat16*)p;
    bool i32 = true, f32 = true, b16 = true;
    for (int i = lane; i < 64; i += 32) {
        int v = ip[i];
        if (v < -128 || v > 127) i32 = false;
        float f = fp[i];
        if (!(f == floorf(f) && f >= -128.f && f <= 127.f)) f32 = false;
    }
    for (int i = lane; i < 128; i += 32) {
        float f = __bfloat162float(bp[i]);
        if (!(f == floorf(f) && f >= -128.f && f <= 127.f)) b16 = false;
    }
    i32 = __all_sync(0xFFFFFFFFu, i32);
    f32 = __all_sync(0xFFFFFFFFu, f32);
    b16 = __all_sync(0xFFFFFFFFu, b16);
    if (i32) return 2;
    if (f32) return 1;
    if (b16) return 3;
    return 0;
}

__device__ static int detect_kind(const void* p, int lane)
{
    const int*   ip = (const int*)p;
    const float* fp = (const float*)p;
    bool i32b = true, f32s = true, f32b = true;
    for (int i = lane; i < 64; i += 32) {
        int v = ip[i];
        if (v < -1000 || v > 1000) i32b = false;
        float f = fp[i];
        if (!(f >= 0.0009f && f <= 0.0101f)) f32s = false;
        if (!(f == floorf(f) && f >= -1000.f && f <= 1000.f)) f32b = false;
    }
    i32b = __all_sync(0xFFFFFFFFu, i32b);
    f32s = __all_sync(0xFFFFFFFFu, f32s);
    f32b = __all_sync(0xFFFFFFFFu, f32b);
    if (i32b) return 0;
    if (f32s) return 2;
    if (f32b) return 1;
    return 2;
}

__global__ void detect_kernel(const void* x, const void* w,
                              const void* s0, const void* s1)
{
    int warp = threadIdx.x >> 5, lane = threadIdx.x & 31;
    if (warp == 0) { int m = detect_mode(x, lane);  if (lane == 0) g_mode_x = m; }
    if (warp == 1) { int m = detect_mode(w, lane);  if (lane == 0) g_mode_w = m; }
    if (warp == 2) { int k = detect_kind(s0, lane); if (lane == 0) g_kind_s0 = k; }
    if (warp == 3) { int k = detect_kind(s1, lane); if (lane == 0) g_kind_s1 = k; }
}

__device__ __forceinline__ int load_elem(const void* p, size_t idx, int mode)
{
    switch (mode) {
        case 1:  return __float2int_rn(((const float*)p)[idx]);
        case 2:  return ((const int*)p)[idx];
        case 3:  return __float2int_rn(__bfloat162float(((const __nv_bfloat16*)p)[idx]));
        default: return ((const int8_t*)p)[idx];
    }
}

// ---------------- prep 1: NCHW -> padded NHWC ----------------
__global__ void pad_nhwc_kernel(const void* __restrict__ x)
{
    __shared__ __align__(16) int8_t smb[CIN * HW];
    int nb = blockIdx.x;
    int n  = nb / HP;
    int hp = nb - n * HP;
    int t  = threadIdx.x;                         // 128 threads
    int mode = g_mode_x;

    int8_t* xprow = g_xp + (size_t)(n * HP + hp) * HP * CIN;

    for (int idx = t; idx < HP * CIN / 16; idx += 128)
        ((int4*)xprow)[idx] = make_int4(0, 0, 0, 0);

    if (hp == 0 || hp == HP - 1) return;
    int h = hp - 1;

    if (mode == 1) {
        // fast path (float32 input): vectorized float4 loads, uchar4 smem stores
        const float* fx = (const float*)x;
        #pragma unroll
        for (int it = 0; it < 14; ++it) {          // 128*14 float4 = CIN*HW elems
            int idx = it * 128 + t;
            int c   = idx / 14;
            int w4  = idx - c * 14;
            const float4 v = *(const float4*)(fx + (size_t)(n * CIN + c) * 3136
                                                 + (size_t)h * HW + w4 * 4);
            uchar4 b;
            b.x = (uint8_t)(int8_t)__float2int_rn(v.x);
            b.y = (uint8_t)(int8_t)__float2int_rn(v.y);
            b.z = (uint8_t)(int8_t)__float2int_rn(v.z);
            b.w = (uint8_t)(int8_t)__float2int_rn(v.w);
            *(uchar4*)(smb + c * HW + w4 * 4) = b;
        }
    } else {
        for (int ii = t; ii < CIN * HW; ii += 128) {
            int c  = ii / HW;
            int wi = ii - c * HW;
            size_t gidx = (size_t)(n * CIN + c) * 3136 + (size_t)h * HW + wi;
            smb[ii] = (int8_t)load_elem(x, gidx, mode);
        }
    }
    __syncthreads();

    #pragma unroll 4
    for (int i = 0; i < HW; ++i)
        xprow[(i + 1) * CIN + t] = smb[t * HW + i];
}

// ---------------- prep 2: OIHW -> [oc][kh][kw][ic] ----------------
__global__ void wt_transform_kernel(const void* __restrict__ w)
{
    int idx = blockIdx.x * 256 + threadIdx.x;
    int mode = g_mode_w;
    int oc  = idx / (KTAPS * CIN);
    int r   = idx - oc * (KTAPS * CIN);
    int tap = r >> 7;
    int ic  = r & 127;
    int kh  = tap / 3, kw = tap - kh * 3;
    size_t gidx = ((size_t)(oc * CIN + ic) * 3 + kh) * 3 + kw;
    g_wt[idx] = (int8_t)load_elem(w, gidx, mode);
}

// ---------------- PTX helpers ----------------
__device__ __forceinline__ void cpa16(uint32_t s, const void* g) {
    asm volatile("cp.async.cg.shared.global [%0], [%1], 16;\n" :: "r"(s), "l"(g));
}
__device__ __forceinline__ void ldm_x4(uint32_t addr, uint32_t& r0, uint32_t& r1,
                                       uint32_t& r2, uint32_t& r3) {
    asm volatile("ldmatrix.sync.aligned.m8n8.x4.shared.b16 {%0,%1,%2,%3}, [%4];\n"
                 : "=r"(r0), "=r"(r1), "=r"(r2), "=r"(r3) : "r"(addr));
}
__device__ __forceinline__ void mma8(int& d0, int& d1, int& d2, int& d3,
                                     uint32_t a0, uint32_t a1, uint32_t a2, uint32_t a3,
                                     uint32_t b0, uint32_t b1) {
    asm volatile("mma.sync.aligned.m16n8k32.row.col.s32.s8.s8.s32 "
                 "{%0,%1,%2,%3}, {%4,%5,%6,%7}, {%8,%9}, {%0,%1,%2,%3};\n"
                 : "+r"(d0), "+r"(d1), "+r"(d2), "+r"(d3)
                 : "r"(a0), "r"(a1), "r"(a2), "r"(a3), "r"(b0), "r"(b1));
}

// ---------------- main: implicit GEMM conv, 4-stage K64 pipeline, 8 warps ----------------
// block tile: 128(M pixels) x 128(N oc); 8 warps in 2(m) x 4(n), warp tile 64x32.
// K = 18 chunks of 64 (9 taps x 2 halves), 3 chunks in flight, 1 sync per chunk.
__global__ void __launch_bounds__(256, 2)
conv_kernel(const void* __restrict__ sA, const void* __restrict__ sB,
            float* __restrict__ out)
{
    extern __shared__ __align__(128) int8_t smem[];
    const int tid  = threadIdx.x;
    const int lane = tid & 31, warp = tid >> 5;
    const int wm = warp & 1, wn = warp >> 1;      // wn in 0..3
    const int bm = blockIdx.y, bn = blockIdx.x;

    uint32_t sbase = (uint32_t)__cvta_generic_to_shared(smem);

    // loader mapping: thread t -> row t>>1, 32B half (t&1) of the 64B chunk row
    const int lrow = tid >> 1;
    const int lofs = (tid & 1) * 32;
    int p  = bm * 128 + lrow;
    int n  = p / 3136;
    int s  = p - n * 3136;
    int oh = s / 56;
    int ow = s - oh * 56;
    const int8_t* abase = g_xp + (size_t)((n * HP + oh) * HP + ow) * CIN + lofs;
    const int8_t* bbase = g_wt + (size_t)(bn * 128 + lrow) * (KTAPS * CIN) + lofs;
    const uint32_t s_row = (uint32_t)(lrow * CROW + lofs);

    int acc[4][4][4];
    #pragma unroll
    for (int i = 0; i < 4; i++)
        #pragma unroll
        for (int j = 0; j < 4; j++)
            #pragma unroll
            for (int r = 0; r < 4; r++) acc[i][j][r] = 0;

    // ldmatrix lane decode
    const int q  = lane >> 3;
    const int lr = lane & 7;
    const int a_row_off  = (q & 1) * 8 + lr;
    const int a_k_off    = (q >> 1) * 16;
    const int b_tile_sel = (q >> 1);
    const int b_k_off    = (q & 1) * 16;

    auto load_chunk = [&](int ci) {
        const int st   = ci & 3;
        const int tap  = ci >> 1;
        const int kofs = (ci & 1) * 64;
        const int kh = tap / 3, kw = tap - kh * 3;
        const uint32_t sa = sbase + st * STAGE + s_row;
        const int8_t* ga = abase + (kh * HP + kw) * CIN + kofs;
        cpa16(sa,      ga);
        cpa16(sa + 16, ga + 16);
        const uint32_t sb = sa + CTILE;
        const int8_t* gb = bbase + tap * CIN + kofs;
        cpa16(sb,      gb);
        cpa16(sb + 16, gb + 16);
        asm volatile("cp.async.commit_group;\n" ::: "memory");
    };

    // prologue: 3 chunks in flight
    load_chunk(0);
    load_chunk(1);
    load_chunk(2);

    for (int ci = 0; ci < NCHUNK; ++ci) {
        // wait for chunk ci (allow the younger in-flight chunks to remain)
        if (ci <= NCHUNK - 3)      asm volatile("cp.async.wait_group 2;\n" ::: "memory");
        else if (ci == NCHUNK - 2) asm volatile("cp.async.wait_group 1;\n" ::: "memory");
        else                       asm volatile("cp.async.wait_group 0;\n" ::: "memory");
        __syncthreads();            // chunk ci visible; slot (ci+3)%4 free

        if (ci + 3 < NCHUNK) load_chunk(ci + 3);   // overlaps compute of ci

        const uint32_t Ab = sbase + (ci & 3) * STAGE;
        const uint32_t Bb = Ab + CTILE;
        #pragma unroll
        for (int ks = 0; ks < 2; ++ks) {
            uint32_t a[4][4];
            #pragma unroll
            for (int i = 0; i < 4; i++) {
                uint32_t addr = Ab + (uint32_t)((wm * 64 + i * 16 + a_row_off) * CROW
                                                + a_k_off + ks * 32);
                ldm_x4(addr, a[i][0], a[i][1], a[i][2], a[i][3]);
            }
            uint32_t b[4][2];
            #pragma unroll
            for (int jp = 0; jp < 2; jp++) {
                uint32_t addr = Bb + (uint32_t)((wn * 32 + (jp * 2 + b_tile_sel) * 8 + lr) * CROW
                                                + b_k_off + ks * 32);
                uint32_t r0, r1, r2, r3;
                ldm_x4(addr, r0, r1, r2, r3);
                b[jp * 2][0] = r0;     b[jp * 2][1] = r1;
                b[jp * 2 + 1][0] = r2; b[jp * 2 + 1][1] = r3;
            }
            #pragma unroll
            for (int i = 0; i < 4; i++)
                #pragma unroll
                for (int j = 0; j < 4; j++)
                    mma8(acc[i][j][0], acc[i][j][1], acc[i][j][2], acc[i][j][3],
                         a[i][0], a[i][1], a[i][2], a[i][3], b[j][0], b[j][1]);
        }
    }
    __syncthreads();   // everyone done reading stages before epilogue reuses smem

    // ---------------- epilogue: requantize -> smem [oc][pixel] -> float32 NCHW ----------------
    const int k0 = g_kind_s0;
    const void* biasp; const float* scalep; int bias_f32;
    if (k0 == 2) { scalep = (const float*)sA; biasp = sB; bias_f32 = (g_kind_s1 == 1); }
    else         { biasp  = sA; bias_f32 = (k0 == 1); scalep = (const float*)sB; }

    float* smf = (float*)smem;
    const int STRF = 132;     // floats; 128*132*4 = 67584 <= 81920
    const int gid = lane >> 2, tig = lane & 3;

    #pragma unroll
    for (int j = 0; j < 4; j++) {
        int col0 = wn * 32 + j * 8 + tig * 2;                 // local oc within 128
        int oc0  = bn * 128 + col0;
        int bv0, bv1;
        if (bias_f32) { bv0 = __float2int_rn(((const float*)biasp)[oc0]);
                        bv1 = __float2int_rn(((const float*)biasp)[oc0 + 1]); }
        else          { bv0 = ((const int*)biasp)[oc0];
                        bv1 = ((const int*)biasp)[oc0 + 1]; }
        float sc0 = (0.02f * scalep[oc0])     / 0.05f;        // reference fp32 op order
        float sc1 = (0.02f * scalep[oc0 + 1]) / 0.05f;
        #pragma unroll
        for (int i = 0; i < 4; i++) {
            #pragma unroll
            for (int r = 0; r < 4; r++) {
                int row = wm * 64 + i * 16 + gid + (r >> 1) * 8;
                int cl  = col0 + (r & 1);
                int v   = acc[i][j][r] + ((r & 1) ? bv1 : bv0);
                float f = (float)v * ((r & 1) ? sc1 : sc0);
                int qv  = __float2int_rn(f);                  // round-half-even
                qv = max(-128, min(127, qv));
                smf[cl * STRF + row] = (float)qv;
            }
        }
    }
    __syncthreads();

    // coalesced writeout: thread t -> oc row t>>1, 64-pixel half (t&1)
    {
        int cl  = tid >> 1;
        int px0 = (tid & 1) * 64;
        int oc  = bn * 128 + cl;
        int pp  = bm * 128 + px0;
        int nn  = pp / 3136;
        int ss  = pp - nn * 3136;                 // 64 | 3136: chunk stays in-image
        float4*       dst = (float4*)(out + ((size_t)(nn * OC + oc)) * 3136 + ss);
        const float4* src = (const float4*)(smf + cl * STRF + px0);
        #pragma unroll
        for (int k = 0; k < 16; k++) dst[k] = src[k];
    }
}

// ---------------- launch ----------------
extern "C" void kernel_launch(void* const* d_in, const int* in_sizes, int n_in,
                              void* d_out, int out_size)
{
    const void* xin = 0; const void* win = 0;
    const void* s0  = 0; const void* s1  = 0;
    for (int i = 0; i < n_in; i++) {
        if (in_sizes[i] == X_ELEMS)      xin = d_in[i];
        else if (in_sizes[i] == W_ELEMS) win = d_in[i];
        else if (!s0)                    s0  = d_in[i];
        else                             s1  = d_in[i];
    }

    detect_kernel<<<1, 128>>>(xin, win, s0, s1);
    wt_transform_kernel<<<(OC * KTAPS * CIN) / 256, 256>>>(win);
    pad_nhwc_kernel<<<NB * HP, 128>>>(xin);

    cudaFuncSetAttribute(conv_kernel, cudaFuncAttributeMaxDynamicSharedMemorySize,
                         SMEM_DYN);
    dim3 grid(OC / 128, MTOT / 128);   // (2, 784)
    conv_kernel<<<grid, 256, SMEM_DYN>>>(s0, s1, (float*)d_out);
}